// round 1
// baseline (speedup 1.0000x reference)
#include <cuda_runtime.h>
#include <math.h>

#define SEQ 2048
#define DM  1024
#define DFF 4096
#define DIN 2048
#define NH  16
#define XPN 96
#define DST 16

// ---------------- scratch (device globals; no runtime allocation) ----------
__device__ float g_ln  [SEQ*DM];
__device__ float g_q   [SEQ*DM];
__device__ float g_k   [SEQ*DM];
__device__ float g_v   [SEQ*DM];
__device__ float g_ao  [SEQ*DM];
__device__ float g_x1  [SEQ*DM];
__device__ float g_ln2 [SEQ*DM];
__device__ float g_xin [SEQ*DIN];
__device__ float g_xc  [SEQ*DIN];
__device__ float g_y   [SEQ*DIN];
__device__ float g_xdbc[SEQ*XPN];
__device__ float g_Bm  [SEQ*DST];
__device__ float g_Cm  [SEQ*DST];
__device__ float g_H   [SEQ*DST];
__device__ float g_sv  [SEQ];
__device__ float g_mt  [SEQ*DM];
__device__ float g_x2  [SEQ*DM];
__device__ float g_ff  [SEQ*DFF];
__device__ float g_M   [256];
__device__ float g_M64 [256];

// ---------------- GEMM: C = A @ W^T (+bias)(+res)(gelu) --------------------
// A: (M,K) row-major, W: (N,K) row-major. 128x128 tile, BK=8, 256 threads.
template<bool GELU, bool RES>
__global__ void __launch_bounds__(256) gemm_k(
    const float* __restrict__ A, const float* __restrict__ W,
    const float* __restrict__ bias, const float* __restrict__ res,
    float* __restrict__ C, int M, int N, int K)
{
    __shared__ float sA[8*132];
    __shared__ float sB[8*132];
    const int tid = threadIdx.x;
    const int tx = tid & 15, ty = tid >> 4;
    const int r2 = tid >> 1, hf = tid & 1;
    const int rowA = blockIdx.y * 128 + r2;
    const int rowB = blockIdx.x * 128 + r2;
    const bool bok = rowB < N;
    const float* Ap = A + (size_t)rowA * K + hf * 4;
    const float* Bp = W + (size_t)rowB * K + hf * 4;

    float acc[8][8];
    #pragma unroll
    for (int i = 0; i < 8; i++)
        #pragma unroll
        for (int j = 0; j < 8; j++) acc[i][j] = 0.f;

    const int nk = K >> 3;
    for (int kt = 0; kt < nk; ++kt) {
        float4 av = *(const float4*)(Ap + (size_t)kt * 8);
        float4 bv = bok ? *(const float4*)(Bp + (size_t)kt * 8)
                        : make_float4(0.f, 0.f, 0.f, 0.f);
        __syncthreads();
        sA[(hf*4+0)*132 + r2] = av.x;
        sA[(hf*4+1)*132 + r2] = av.y;
        sA[(hf*4+2)*132 + r2] = av.z;
        sA[(hf*4+3)*132 + r2] = av.w;
        sB[(hf*4+0)*132 + r2] = bv.x;
        sB[(hf*4+1)*132 + r2] = bv.y;
        sB[(hf*4+2)*132 + r2] = bv.z;
        sB[(hf*4+3)*132 + r2] = bv.w;
        __syncthreads();
        #pragma unroll
        for (int kk = 0; kk < 8; ++kk) {
            float4 a0 = *(const float4*)&sA[kk*132 + ty*8];
            float4 a1 = *(const float4*)&sA[kk*132 + ty*8 + 4];
            float4 b0 = *(const float4*)&sB[kk*132 + tx*8];
            float4 b1 = *(const float4*)&sB[kk*132 + tx*8 + 4];
            float a[8] = {a0.x,a0.y,a0.z,a0.w,a1.x,a1.y,a1.z,a1.w};
            float b[8] = {b0.x,b0.y,b0.z,b0.w,b1.x,b1.y,b1.z,b1.w};
            #pragma unroll
            for (int i = 0; i < 8; i++)
                #pragma unroll
                for (int j = 0; j < 8; j++)
                    acc[i][j] = fmaf(a[i], b[j], acc[i][j]);
        }
    }
    #pragma unroll
    for (int i = 0; i < 8; i++) {
        int r = blockIdx.y * 128 + ty * 8 + i;
        #pragma unroll
        for (int j = 0; j < 8; j++) {
            int c = blockIdx.x * 128 + tx * 8 + j;
            if (c < N) {
                float v = acc[i][j];
                if (bias) v += bias[c];
                if (RES)  v += res[(size_t)r * N + c];
                if (GELU) {
                    float u = v;
                    v = 0.5f * u * (1.f + tanhf(0.7978845608f * (u + 0.044715f*u*u*u)));
                }
                C[(size_t)r * N + c] = v;
            }
        }
    }
}

// ---------------- fused attention (flash-style, fp32) ----------------------
// grid (SEQ/64, NH), 256 threads. Q,K,V,O: (SEQ, 1024), head h at cols h*64..
__global__ void __launch_bounds__(256) attn_k(
    const float* __restrict__ Q, const float* __restrict__ K,
    const float* __restrict__ V, float* __restrict__ O)
{
    extern __shared__ float sm[];
    float* QT = sm;             // [64 d][68] transposed
    float* KT = QT + 64*68;     // [64 d][68] transposed
    float* Vs = KT + 64*68;     // [64 key][68]
    float* Ps = Vs + 64*68;     // [64 row][68]
    float* rm = Ps + 64*68;     // 64
    float* rl = rm + 64;        // 64
    float* rs = rl + 64;        // 64

    const int tid = threadIdx.x;
    const int tx = tid & 15, ty = tid >> 4;
    const int q0 = blockIdx.x * 64;
    const int cbase = blockIdx.y * 64;

    {   // load Q tile transposed
        int r = tid >> 2, seg = tid & 3;
        const float* qp = Q + (size_t)(q0 + r) * DM + cbase + seg * 16;
        #pragma unroll
        for (int u = 0; u < 4; u++) {
            float4 qv = *(const float4*)(qp + u * 4);
            int c = seg * 16 + u * 4;
            QT[(c+0)*68 + r] = qv.x;
            QT[(c+1)*68 + r] = qv.y;
            QT[(c+2)*68 + r] = qv.z;
            QT[(c+3)*68 + r] = qv.w;
        }
    }
    if (tid < 64) { rm[tid] = -1e30f; rl[tid] = 0.f; }
    float oacc[4][4];
    #pragma unroll
    for (int i = 0; i < 4; i++)
        #pragma unroll
        for (int j = 0; j < 4; j++) oacc[i][j] = 0.f;

    for (int kt = 0; kt < SEQ/64; kt++) {
        __syncthreads();
        {   // load K transposed + V direct
            int r = tid >> 2, seg = tid & 3;
            const float* kp = K + (size_t)(kt*64 + r) * DM + cbase + seg * 16;
            const float* vp = V + (size_t)(kt*64 + r) * DM + cbase + seg * 16;
            #pragma unroll
            for (int u = 0; u < 4; u++) {
                float4 kv = *(const float4*)(kp + u * 4);
                int c = seg * 16 + u * 4;
                KT[(c+0)*68 + r] = kv.x;
                KT[(c+1)*68 + r] = kv.y;
                KT[(c+2)*68 + r] = kv.z;
                KT[(c+3)*68 + r] = kv.w;
                float4 vv = *(const float4*)(vp + u * 4);
                *(float4*)&Vs[r*68 + c] = vv;
            }
        }
        __syncthreads();
        // S = Q K^T
        float s[4][4];
        #pragma unroll
        for (int i = 0; i < 4; i++)
            #pragma unroll
            for (int j = 0; j < 4; j++) s[i][j] = 0.f;
        #pragma unroll 4
        for (int d = 0; d < 64; d++) {
            float4 qv = *(const float4*)&QT[d*68 + ty*4];
            float4 kv = *(const float4*)&KT[d*68 + tx*4];
            float qf[4] = {qv.x, qv.y, qv.z, qv.w};
            float kf[4] = {kv.x, kv.y, kv.z, kv.w};
            #pragma unroll
            for (int i = 0; i < 4; i++)
                #pragma unroll
                for (int j = 0; j < 4; j++)
                    s[i][j] = fmaf(qf[i], kf[j], s[i][j]);
        }
        #pragma unroll
        for (int i = 0; i < 4; i++)
            #pragma unroll
            for (int j = 0; j < 4; j++)
                Ps[(ty*4+i)*68 + tx*4 + j] = s[i][j] * 0.125f;
        __syncthreads();
        // online softmax per row
        {
            int r = tid >> 2, sub = tid & 3;
            float* prow = Ps + r*68 + sub*16;
            float tm = -1e30f;
            #pragma unroll
            for (int c = 0; c < 16; c++) tm = fmaxf(tm, prow[c]);
            tm = fmaxf(tm, __shfl_xor_sync(0xffffffffu, tm, 1));
            tm = fmaxf(tm, __shfl_xor_sync(0xffffffffu, tm, 2));
            float mold = rm[r];
            float mnew = fmaxf(mold, tm);
            float lsum = 0.f;
            #pragma unroll
            for (int c = 0; c < 16; c++) {
                float p = __expf(prow[c] - mnew);
                prow[c] = p;
                lsum += p;
            }
            lsum += __shfl_xor_sync(0xffffffffu, lsum, 1);
            lsum += __shfl_xor_sync(0xffffffffu, lsum, 2);
            if (sub == 0) {
                float sc = __expf(mold - mnew);
                rs[r] = sc;
                rm[r] = mnew;
                rl[r] = rl[r] * sc + lsum;
            }
        }
        __syncthreads();
        // rescale + O += P@V
        float scl[4];
        #pragma unroll
        for (int i = 0; i < 4; i++) scl[i] = rs[ty*4+i];
        #pragma unroll
        for (int i = 0; i < 4; i++)
            #pragma unroll
            for (int j = 0; j < 4; j++) oacc[i][j] *= scl[i];
        for (int kk = 0; kk < 64; kk++) {
            float pf[4];
            #pragma unroll
            for (int i = 0; i < 4; i++) pf[i] = Ps[(ty*4+i)*68 + kk];
            float4 vv = *(const float4*)&Vs[kk*68 + tx*4];
            float vf[4] = {vv.x, vv.y, vv.z, vv.w};
            #pragma unroll
            for (int i = 0; i < 4; i++)
                #pragma unroll
                for (int j = 0; j < 4; j++)
                    oacc[i][j] = fmaf(pf[i], vf[j], oacc[i][j]);
        }
    }
    float linv[4];
    #pragma unroll
    for (int i = 0; i < 4; i++) linv[i] = 1.f / rl[ty*4+i];
    #pragma unroll
    for (int i = 0; i < 4; i++)
        #pragma unroll
        for (int j = 0; j < 4; j++)
            O[(size_t)(q0 + ty*4 + i) * DM + cbase + tx*4 + j] = oacc[i][j] * linv[i];
}

// ---------------- LayerNorm (W=1024), optional affine / residual add -------
template<bool AFF, bool RES>
__global__ void __launch_bounds__(256) ln_k(
    const float* __restrict__ X, const float* __restrict__ g,
    const float* __restrict__ b, const float* __restrict__ res,
    float* __restrict__ Y)
{
    const int row = blockIdx.x;
    const float* x = X + (size_t)row * DM;
    const int tid = threadIdx.x;
    float v[4];
    float s = 0.f;
    #pragma unroll
    for (int u = 0; u < 4; u++) { v[u] = x[tid + 256*u]; s += v[u]; }
    __shared__ float red[8];
    __shared__ float stat[2];
    #pragma unroll
    for (int off = 16; off; off >>= 1) s += __shfl_xor_sync(0xffffffffu, s, off);
    if ((tid & 31) == 0) red[tid >> 5] = s;
    __syncthreads();
    if (tid == 0) {
        float t = 0.f;
        for (int k2 = 0; k2 < 8; k2++) t += red[k2];
        stat[0] = t * (1.f/1024.f);
    }
    __syncthreads();
    float mu = stat[0];
    float q = 0.f;
    #pragma unroll
    for (int u = 0; u < 4; u++) { float d = v[u] - mu; q += d*d; }
    #pragma unroll
    for (int off = 16; off; off >>= 1) q += __shfl_xor_sync(0xffffffffu, q, off);
    if ((tid & 31) == 0) red[tid >> 5] = q;
    __syncthreads();
    if (tid == 0) {
        float t = 0.f;
        for (int k2 = 0; k2 < 8; k2++) t += red[k2];
        stat[1] = rsqrtf(t * (1.f/1024.f) + 1e-5f);
    }
    __syncthreads();
    float rstd = stat[1];
    float* y = Y + (size_t)row * DM;
    #pragma unroll
    for (int u = 0; u < 4; u++) {
        int c = tid + 256*u;
        float o = (v[u] - mu) * rstd;
        if (AFF) o = o * g[c] + b[c];
        if (RES) o += res[(size_t)row * DM + c];
        y[c] = o;
    }
}

// ---------------- depthwise causal conv1d (k=4) ----------------------------
__global__ void conv_k(const float* __restrict__ cw, const float* __restrict__ cb)
{
    int idx = blockIdx.x * blockDim.x + threadIdx.x;
    if (idx >= SEQ * DIN) return;
    int t = idx >> 11, c = idx & (DIN - 1);
    float acc = cb[c];
    #pragma unroll
    for (int k = 0; k < 4; k++) {
        int ts = t + k - 3;
        if (ts >= 0) acc = fmaf(cw[c*4 + k], g_xin[(size_t)ts * DIN + c], acc);
    }
    g_xc[idx] = acc;
}

// ---------------- B/C extraction: LN96 then LN16 (exact reference math) ----
__global__ void bc_k()
{
    const int row = blockIdx.x;
    const int lane = threadIdx.x;
    const float* xr = g_xdbc + (size_t)row * XPN;
    float a0 = xr[lane], a1 = xr[lane + 32], a2 = xr[lane + 64];
    float s = a0 + a1 + a2;
    #pragma unroll
    for (int off = 16; off; off >>= 1) s += __shfl_xor_sync(0xffffffffu, s, off);
    float mu = s * (1.f/96.f);
    float d0 = a0-mu, d1 = a1-mu, d2 = a2-mu;
    float q = d0*d0 + d1*d1 + d2*d2;
    #pragma unroll
    for (int off = 16; off; off >>= 1) q += __shfl_xor_sync(0xffffffffu, q, off);
    float rstd = rsqrtf(q * (1.f/96.f) + 1e-5f);
    // cols 64..95 normalized by LN96
    float vv = d2 * rstd;
    // LN16 within each 16-lane half (xor<16 stays inside half)
    float hs = vv;
    #pragma unroll
    for (int off = 8; off; off >>= 1) hs += __shfl_xor_sync(0xffffffffu, hs, off);
    float m16 = hs * (1.f/16.f);
    float dd = vv - m16;
    float qq = dd * dd;
    #pragma unroll
    for (int off = 8; off; off >>= 1) qq += __shfl_xor_sync(0xffffffffu, qq, off);
    float o = dd * rsqrtf(qq * (1.f/16.f) + 1e-5f);
    if (lane < 16) g_Bm[row*16 + lane] = o;
    else           g_Cm[row*16 + lane - 16] = o;
}

// ---------------- build M and M^64 (delta cancels; M is constant) ----------
__global__ void __launch_bounds__(256) buildM_k(const float* __restrict__ A)
{
    __shared__ float sred[256], sP[256];
    const int t = threadIdx.x;
    const int i = t >> 4, j = t & 15;
    float la = logf(fabsf(A[j*16 + i]) + 1e-8f);   // logA[i][j] = log|A[j][i]|
    sred[t] = la;
    __syncthreads();
    for (int off = 128; off > 0; off >>= 1) {
        if (t < off) sred[t] = fminf(sred[t], sred[t + off]);
        __syncthreads();
    }
    float mn = sred[0];
    float Mv = expf(mn - la);
    Mv = fminf(fmaxf(Mv, 1e-4f), 1e4f);
    g_M[t] = Mv;
    sP[t] = Mv;
    __syncthreads();
    for (int it = 0; it < 6; ++it) {           // M^2,4,8,16,32,64
        float acc = 0.f;
        #pragma unroll
        for (int k = 0; k < 16; k++) acc = fmaf(sP[i*16 + k], sP[k*16 + j], acc);
        __syncthreads();
        sP[t] = acc;
        __syncthreads();
    }
    g_M64[t] = sP[t];
}

// ---------------- chunked parallel scan: H_t = M H_{t-1} + B_t -------------
// One block, 32 warps; each warp owns a 64-step chunk; lane i holds H[i].
__global__ void __launch_bounds__(1024) scan_k()
{
    __shared__ float sM[256], sM64[256], sE[32*16], sS[32*16];
    const int tid = threadIdx.x;
    if (tid < 256) { sM[tid] = g_M[tid]; sM64[tid] = g_M64[tid]; }
    __syncthreads();
    const int w = tid >> 5, lane = tid & 31;
    float mrow[16];
    #pragma unroll
    for (int j = 0; j < 16; j++) mrow[j] = (lane < 16) ? sM[lane*16 + j] : 0.f;
    const int t0 = w * 64;
    // phase A: local scan (zero initial state)
    float h = 0.f;
    for (int k = 0; k < 64; k++) {
        float acc = (lane < 16) ? g_Bm[(t0 + k)*16 + lane] : 0.f;
        #pragma unroll
        for (int j = 0; j < 16; j++)
            acc = fmaf(mrow[j], __shfl_sync(0xffffffffu, h, j), acc);
        h = acc;
        if (lane < 16) g_H[(t0 + k)*16 + lane] = h;
    }
    if (lane < 16) sE[w*16 + lane] = h;
    __syncthreads();
    // phase B: combine chunk-end states with M^64 (warp 0, serial over 32)
    if (w == 0) {
        float m64row[16];
        #pragma unroll
        for (int j = 0; j < 16; j++) m64row[j] = (lane < 16) ? sM64[lane*16 + j] : 0.f;
        float sv2 = (lane < 16) ? sE[lane] : 0.f;
        if (lane < 16) sS[lane] = sv2;
        for (int c = 1; c < 32; c++) {
            float acc = (lane < 16) ? sE[c*16 + lane] : 0.f;
            #pragma unroll
            for (int j = 0; j < 16; j++)
                acc = fmaf(m64row[j], __shfl_sync(0xffffffffu, sv2, j), acc);
            sv2 = acc;
            if (lane < 16) sS[c*16 + lane] = sv2;
        }
    }
    __syncthreads();
    // phase C: H_t = L_t + M^{k+1} S_{c-1}; emit s_t = H_t . Cm_t
    float v = (w > 0 && lane < 16) ? sS[(w-1)*16 + lane] : 0.f;
    for (int k = 0; k < 64; k++) {
        if (w > 0) {
            float acc = 0.f;
            #pragma unroll
            for (int j = 0; j < 16; j++)
                acc = fmaf(mrow[j], __shfl_sync(0xffffffffu, v, j), acc);
            v = acc;
        }
        float hh = 0.f, cc = 0.f;
        if (lane < 16) {
            hh = g_H[(t0 + k)*16 + lane] + v;
            cc = g_Cm[(t0 + k)*16 + lane];
        }
        float p = hh * cc;
        p += __shfl_xor_sync(0xffffffffu, p, 8);
        p += __shfl_xor_sync(0xffffffffu, p, 4);
        p += __shfl_xor_sync(0xffffffffu, p, 2);
        p += __shfl_xor_sync(0xffffffffu, p, 1);
        if (lane == 0) g_sv[t0 + k] = p;
    }
}

// ---------------- y = clip(x_in * (s + Dp), +-1000) ------------------------
__global__ void y_k(const float* __restrict__ Dp)
{
    int idx = blockIdx.x * blockDim.x + threadIdx.x;
    if (idx >= SEQ * DIN) return;
    int t = idx >> 11, c = idx & (DIN - 1);
    float vv = g_xin[idx] * (g_sv[t] + Dp[c]);
    g_y[idx] = fminf(fmaxf(vv, -1000.f), 1000.f);
}

// ---------------------------------------------------------------------------
extern "C" void kernel_launch(void* const* d_in, const int* in_sizes, int n_in,
                              void* d_out, int out_size)
{
    const float* x     = (const float*)d_in[0];
    const float* Wq    = (const float*)d_in[1];
    const float* bq    = (const float*)d_in[2];
    const float* Wk    = (const float*)d_in[3];
    const float* bk    = (const float*)d_in[4];
    const float* Wv    = (const float*)d_in[5];
    const float* bv    = (const float*)d_in[6];
    const float* Wo    = (const float*)d_in[7];
    const float* bo    = (const float*)d_in[8];
    const float* fc1w  = (const float*)d_in[9];
    const float* fc1b  = (const float*)d_in[10];
    const float* fc2w  = (const float*)d_in[11];
    const float* fc2b  = (const float*)d_in[12];
    const float* inw   = (const float*)d_in[13];
    const float* inb   = (const float*)d_in[14];
    const float* convw = (const float*)d_in[15];
    const float* convb = (const float*)d_in[16];
    const float* xpw   = (const float*)d_in[17];
    const float* xpb   = (const float*)d_in[18];
    const float* Amat  = (const float*)d_in[19];
    const float* Dp    = (const float*)d_in[20];
    // d_in[21] = dt_p: provably dead (delta cancels in the scan transition)
    const float* outw  = (const float*)d_in[22];
    const float* outb  = (const float*)d_in[23];
    const float* g1    = (const float*)d_in[24];
    const float* be1   = (const float*)d_in[25];
    const float* g2    = (const float*)d_in[26];
    const float* be2   = (const float*)d_in[27];
    const float* g3    = (const float*)d_in[28];
    const float* be3   = (const float*)d_in[29];
    float* out = (float*)d_out;

    float *p_ln, *p_q, *p_k, *p_v, *p_ao, *p_x1, *p_ln2, *p_xin, *p_xc,
          *p_xdbc, *p_y, *p_mt, *p_x2, *p_ff;
    cudaGetSymbolAddress((void**)&p_ln,   g_ln);
    cudaGetSymbolAddress((void**)&p_q,    g_q);
    cudaGetSymbolAddress((void**)&p_k,    g_k);
    cudaGetSymbolAddress((void**)&p_v,    g_v);
    cudaGetSymbolAddress((void**)&p_ao,   g_ao);
    cudaGetSymbolAddress((void**)&p_x1,   g_x1);
    cudaGetSymbolAddress((void**)&p_ln2,  g_ln2);
    cudaGetSymbolAddress((void**)&p_xin,  g_xin);
    cudaGetSymbolAddress((void**)&p_xc,   g_xc);
    cudaGetSymbolAddress((void**)&p_xdbc, g_xdbc);
    cudaGetSymbolAddress((void**)&p_y,    g_y);
    cudaGetSymbolAddress((void**)&p_mt,   g_mt);
    cudaGetSymbolAddress((void**)&p_x2,   g_x2);
    cudaGetSymbolAddress((void**)&p_ff,   g_ff);

    const int ATTN_SMEM = (4*64*68 + 3*64) * (int)sizeof(float);
    cudaFuncSetAttribute(attn_k, cudaFuncAttributeMaxDynamicSharedMemorySize, ATTN_SMEM);

    // --- block 1: attention ---
    ln_k<true,false><<<SEQ, 256>>>(x, g1, be1, nullptr, p_ln);
    gemm_k<false,false><<<dim3(8,16), 256>>>(p_ln, Wq, bq, nullptr, p_q, SEQ, DM, DM);
    gemm_k<false,false><<<dim3(8,16), 256>>>(p_ln, Wk, bk, nullptr, p_k, SEQ, DM, DM);
    gemm_k<false,false><<<dim3(8,16), 256>>>(p_ln, Wv, bv, nullptr, p_v, SEQ, DM, DM);
    attn_k<<<dim3(SEQ/64, NH), 256, ATTN_SMEM>>>(p_q, p_k, p_v, p_ao);
    gemm_k<false,true><<<dim3(8,16), 256>>>(p_ao, Wo, bo, x, p_x1, SEQ, DM, DM);

    // --- block 2: mamba ---
    ln_k<true,false><<<SEQ, 256>>>(p_x1, g2, be2, nullptr, p_ln);
    ln_k<false,false><<<SEQ, 256>>>(p_ln, nullptr, nullptr, nullptr, p_ln2);
    gemm_k<false,false><<<dim3(16,16), 256>>>(p_ln2, inw, inb, nullptr, p_xin, SEQ, DIN, DM);
    conv_k<<<SEQ*DIN/256, 256>>>(convw, convb);
    gemm_k<false,false><<<dim3(1,16), 256>>>(p_xc, xpw, xpb, nullptr, p_xdbc, SEQ, XPN, DIN);
    bc_k<<<SEQ, 32>>>();
    buildM_k<<<1, 256>>>(Amat);
    scan_k<<<1, 1024>>>();
    y_k<<<SEQ*DIN/256, 256>>>(Dp);
    gemm_k<false,false><<<dim3(8,16), 256>>>(p_y, outw, outb, nullptr, p_mt, SEQ, DM, DIN);
    ln_k<false,true><<<SEQ, 256>>>(p_mt, nullptr, nullptr, p_x1, p_x2);

    // --- block 3: FFN ---
    ln_k<true,false><<<SEQ, 256>>>(p_x2, g3, be3, nullptr, p_ln);
    gemm_k<true,false><<<dim3(32,16), 256>>>(p_ln, fc1w, fc1b, nullptr, p_ff, SEQ, DFF, DM);
    gemm_k<false,true><<<dim3(8,16), 256>>>(p_ff, fc2w, fc2b, p_x2, out, SEQ, DM, DFF);
}

// round 5
// speedup vs baseline: 1.4532x; 1.4532x over previous
#include <cuda_runtime.h>
#include <math.h>

#define SEQ 2048
#define DM  1024
#define DFF 4096
#define DIN 2048
#define NH  16
#define XPN 96
#define DST 16

// ---------------- scratch (device globals; no runtime allocation) ----------
__device__ float g_ln  [SEQ*DM];
__device__ float g_q   [SEQ*DM];
__device__ float g_k   [SEQ*DM];
__device__ float g_v   [SEQ*DM];
__device__ float g_ao  [SEQ*DM];
__device__ float g_x1  [SEQ*DM];
__device__ float g_ln2 [SEQ*DM];
__device__ float g_xin [SEQ*DIN];
__device__ float g_xc  [SEQ*DIN];
__device__ float g_y   [SEQ*DIN];
__device__ float g_xdbc[SEQ*XPN];
__device__ float g_Bm  [SEQ*DST];
__device__ float g_Cm  [SEQ*DST];
__device__ float g_H   [SEQ*DST];
__device__ float g_sv  [SEQ];
__device__ float g_mt  [SEQ*DM];
__device__ float g_x2  [SEQ*DM];
__device__ float g_ff  [SEQ*DFF];
__device__ float g_M   [256];
__device__ float g_M64 [256];

// ---------------- TF32 helpers ---------------------------------------------
__device__ __forceinline__ unsigned f2tf(float f) {
    unsigned u;
    asm("cvt.rna.tf32.f32 %0, %1;" : "=r"(u) : "f"(f));
    return u;
}

// split a into hi (tf32) + lo (tf32 of residual): a ~= hi + lo to ~21 bits
__device__ __forceinline__ void split_tf(float v, unsigned& h, unsigned& l) {
    h = f2tf(v);
    l = f2tf(v - __uint_as_float(h));
}

__device__ __forceinline__ void mma_tf32(float* d, const unsigned* a,
                                         const unsigned* b, const float* c) {
    asm volatile(
        "mma.sync.aligned.m16n8k8.row.col.f32.tf32.tf32.f32 "
        "{%0,%1,%2,%3}, {%4,%5,%6,%7}, {%8,%9}, {%10,%11,%12,%13};\n"
        : "=f"(d[0]), "=f"(d[1]), "=f"(d[2]), "=f"(d[3])
        : "r"(a[0]), "r"(a[1]), "r"(a[2]), "r"(a[3]),
          "r"(b[0]), "r"(b[1]),
          "f"(c[0]), "f"(c[1]), "f"(c[2]), "f"(c[3]));
}

// ------- 3xTF32 tensor-core GEMM: C = A @ W^T (+bias)(+res)(gelu) ----------
// A: (M,K) row-major fp32, W: (N,K) row-major fp32. Tile 128x128, BK=16.
// 256 threads = 2x4 warps; warp computes 64x32 via 4x4 m16n8k8 MMAs.
// Each operand split hi/lo (tf32); acc += Ah*Bh + Al*Bh + Ah*Bl (~fp32 acc).
// Smem row stride 20 -> conflict-free fragment loads. Dynamic smem 80KB.
#define SST 20
#define PER (128*SST)
template<bool GELU, bool RES>
__global__ void __launch_bounds__(256) gemm_k(
    const float* __restrict__ A, const float* __restrict__ W,
    const float* __restrict__ bias, const float* __restrict__ res,
    float* __restrict__ C, int M, int N, int K)
{
    extern __shared__ unsigned smem[];   // [2 buf][Ah,Al,Bh,Bl][PER]
    const int tid  = threadIdx.x;
    const int warp = tid >> 5, lane = tid & 31;
    const int g = lane >> 2, tig = lane & 3;
    const int wm = warp >> 2, wn = warp & 3;
    const int bm = blockIdx.y * 128, bn = blockIdx.x * 128;

    const int lr = tid >> 2, lc = (tid & 3) * 4;
    const float* Ap0 = A + (size_t)(bm + lr) * K + lc;
    const float* Ap1 = Ap0 + (size_t)64 * K;
    const int rB0 = bn + lr, rB1 = bn + lr + 64;
    const bool bok0 = rB0 < N, bok1 = rB1 < N;
    const float* Bp0 = W + (size_t)rB0 * K + lc;
    const float* Bp1 = W + (size_t)rB1 * K + lc;

    float acc[4][4][4];
    #pragma unroll
    for (int i = 0; i < 4; i++)
        #pragma unroll
        for (int j = 0; j < 4; j++)
            #pragma unroll
            for (int r = 0; r < 4; r++) acc[i][j][r] = 0.f;

    const int nk = K >> 4;
    float4 av0, av1, bv0, bv1;

    // store one tile (registers -> smem buf) with hi/lo split
    auto stash = [&](int buf) {
        unsigned* Ah = smem + buf*4*PER;
        unsigned* Al = Ah + PER;
        unsigned* Bh = Al + PER;
        unsigned* Bl = Bh + PER;
        const int o0 = lr*SST + lc, o1 = (lr+64)*SST + lc;
        split_tf(av0.x, Ah[o0+0], Al[o0+0]); split_tf(av0.y, Ah[o0+1], Al[o0+1]);
        split_tf(av0.z, Ah[o0+2], Al[o0+2]); split_tf(av0.w, Ah[o0+3], Al[o0+3]);
        split_tf(av1.x, Ah[o1+0], Al[o1+0]); split_tf(av1.y, Ah[o1+1], Al[o1+1]);
        split_tf(av1.z, Ah[o1+2], Al[o1+2]); split_tf(av1.w, Ah[o1+3], Al[o1+3]);
        split_tf(bv0.x, Bh[o0+0], Bl[o0+0]); split_tf(bv0.y, Bh[o0+1], Bl[o0+1]);
        split_tf(bv0.z, Bh[o0+2], Bl[o0+2]); split_tf(bv0.w, Bh[o0+3], Bl[o0+3]);
        split_tf(bv1.x, Bh[o1+0], Bl[o1+0]); split_tf(bv1.y, Bh[o1+1], Bl[o1+1]);
        split_tf(bv1.z, Bh[o1+2], Bl[o1+2]); split_tf(bv1.w, Bh[o1+3], Bl[o1+3]);
    };

    // prologue
    av0 = *(const float4*)(Ap0);
    av1 = *(const float4*)(Ap1);
    bv0 = bok0 ? *(const float4*)(Bp0) : make_float4(0.f,0.f,0.f,0.f);
    bv1 = bok1 ? *(const float4*)(Bp1) : make_float4(0.f,0.f,0.f,0.f);
    stash(0);
    __syncthreads();

    for (int kt = 0; kt < nk; ++kt) {
        const int buf = kt & 1;
        if (kt + 1 < nk) {
            const size_t off = (size_t)(kt + 1) * 16;
            av0 = *(const float4*)(Ap0 + off);
            av1 = *(const float4*)(Ap1 + off);
            bv0 = bok0 ? *(const float4*)(Bp0 + off) : make_float4(0.f,0.f,0.f,0.f);
            bv1 = bok1 ? *(const float4*)(Bp1 + off) : make_float4(0.f,0.f,0.f,0.f);
        }
        const unsigned* Ah = smem + buf*4*PER;
        const unsigned* Al = Ah + PER;
        const unsigned* Bh = Al + PER;
        const unsigned* Bl = Bh + PER;
        #pragma unroll
        for (int ks = 0; ks < 2; ++ks) {
            const int kk = ks * 8;
            unsigned ah[4][4], al[4][4], bh[4][2], bl[4][2];
            #pragma unroll
            for (int i = 0; i < 4; i++) {
                const int o = (wm*64 + i*16 + g)*SST + kk + tig;
                ah[i][0] = Ah[o];          ah[i][1] = Ah[o + 8*SST];
                ah[i][2] = Ah[o + 4];      ah[i][3] = Ah[o + 8*SST + 4];
                al[i][0] = Al[o];          al[i][1] = Al[o + 8*SST];
                al[i][2] = Al[o + 4];      al[i][3] = Al[o + 8*SST + 4];
            }
            #pragma unroll
            for (int j = 0; j < 4; j++) {
                const int o = (wn*32 + j*8 + g)*SST + kk + tig;
                bh[j][0] = Bh[o];  bh[j][1] = Bh[o + 4];
                bl[j][0] = Bl[o];  bl[j][1] = Bl[o + 4];
            }
            #pragma unroll
            for (int i = 0; i < 4; i++)
                #pragma unroll
                for (int j = 0; j < 4; j++) {
                    mma_tf32(acc[i][j], ah[i], bh[j], acc[i][j]);
                    mma_tf32(acc[i][j], al[i], bh[j], acc[i][j]);
                    mma_tf32(acc[i][j], ah[i], bl[j], acc[i][j]);
                }
        }
        if (kt + 1 < nk) {
            stash(buf ^ 1);
            __syncthreads();
        }
    }

    // epilogue
    #pragma unroll
    for (int i = 0; i < 4; i++) {
        const int r0 = bm + wm*64 + i*16 + g;
        const int r1 = r0 + 8;
        #pragma unroll
        for (int j = 0; j < 4; j++) {
            const int c = bn + wn*32 + j*8 + 2*tig;
            if (c < N) {
                float v0 = acc[i][j][0], v1 = acc[i][j][1];
                float v2 = acc[i][j][2], v3 = acc[i][j][3];
                if (bias) {
                    const float b0 = bias[c], b1 = bias[c+1];
                    v0 += b0; v1 += b1; v2 += b0; v3 += b1;
                }
                if (RES) {
                    v0 += res[(size_t)r0*N + c];
                    v1 += res[(size_t)r0*N + c + 1];
                    v2 += res[(size_t)r1*N + c];
                    v3 += res[(size_t)r1*N + c + 1];
                }
                if (GELU) {
                    #define GLU(u) (0.5f*(u)*(1.f + tanhf(0.7978845608f*((u) + 0.044715f*(u)*(u)*(u)))))
                    v0 = GLU(v0); v1 = GLU(v1); v2 = GLU(v2); v3 = GLU(v3);
                    #undef GLU
                }
                *(float2*)&C[(size_t)r0*N + c] = make_float2(v0, v1);
                *(float2*)&C[(size_t)r1*N + c] = make_float2(v2, v3);
            }
        }
    }
}

// ---------------- fused attention (flash-style, fp32) ----------------------
__global__ void __launch_bounds__(256) attn_k(
    const float* __restrict__ Q, const float* __restrict__ K,
    const float* __restrict__ V, float* __restrict__ O)
{
    extern __shared__ float sm[];
    float* QT = sm;             // [64 d][68] transposed
    float* KT = QT + 64*68;     // [64 d][68] transposed
    float* Vs = KT + 64*68;     // [64 key][68]
    float* Ps = Vs + 64*68;     // [64 row][68]
    float* rm = Ps + 64*68;     // 64
    float* rl = rm + 64;        // 64
    float* rs = rl + 64;        // 64

    const int tid = threadIdx.x;
    const int tx = tid & 15, ty = tid >> 4;
    const int q0 = blockIdx.x * 64;
    const int cbase = blockIdx.y * 64;

    {   // load Q tile transposed
        int r = tid >> 2, seg = tid & 3;
        const float* qp = Q + (size_t)(q0 + r) * DM + cbase + seg * 16;
        #pragma unroll
        for (int u = 0; u < 4; u++) {
            float4 qv = *(const float4*)(qp + u * 4);
            int c = seg * 16 + u * 4;
            QT[(c+0)*68 + r] = qv.x;
            QT[(c+1)*68 + r] = qv.y;
            QT[(c+2)*68 + r] = qv.z;
            QT[(c+3)*68 + r] = qv.w;
        }
    }
    if (tid < 64) { rm[tid] = -1e30f; rl[tid] = 0.f; }
    float oacc[4][4];
    #pragma unroll
    for (int i = 0; i < 4; i++)
        #pragma unroll
        for (int j = 0; j < 4; j++) oacc[i][j] = 0.f;

    for (int kt = 0; kt < SEQ/64; kt++) {
        __syncthreads();
        {   // load K transposed + V direct
            int r = tid >> 2, seg = tid & 3;
            const float* kp = K + (size_t)(kt*64 + r) * DM + cbase + seg * 16;
            const float* vp = V + (size_t)(kt*64 + r) * DM + cbase + seg * 16;
            #pragma unroll
            for (int u = 0; u < 4; u++) {
                float4 kv = *(const float4*)(kp + u * 4);
                int c = seg * 16 + u * 4;
                KT[(c+0)*68 + r] = kv.x;
                KT[(c+1)*68 + r] = kv.y;
                KT[(c+2)*68 + r] = kv.z;
                KT[(c+3)*68 + r] = kv.w;
                float4 vv = *(const float4*)(vp + u * 4);
                *(float4*)&Vs[r*68 + c] = vv;
            }
        }
        __syncthreads();
        float s[4][4];
        #pragma unroll
        for (int i = 0; i < 4; i++)
            #pragma unroll
            for (int j = 0; j < 4; j++) s[i][j] = 0.f;
        #pragma unroll 4
        for (int d = 0; d < 64; d++) {
            float4 qv = *(const float4*)&QT[d*68 + ty*4];
            float4 kv = *(const float4*)&KT[d*68 + tx*4];
            float qf[4] = {qv.x, qv.y, qv.z, qv.w};
            float kf[4] = {kv.x, kv.y, kv.z, kv.w};
            #pragma unroll
            for (int i = 0; i < 4; i++)
                #pragma unroll
                for (int j = 0; j < 4; j++)
                    s[i][j] = fmaf(qf[i], kf[j], s[i][j]);
        }
        #pragma unroll
        for (int i = 0; i < 4; i++)
            #pragma unroll
            for (int j = 0; j < 4; j++)
                Ps[(ty*4+i)*68 + tx*4 + j] = s[i][j] * 0.125f;
        __syncthreads();
        {
            int r = tid >> 2, sub = tid & 3;
            float* prow = Ps + r*68 + sub*16;
            float tm = -1e30f;
            #pragma unroll
            for (int c = 0; c < 16; c++) tm = fmaxf(tm, prow[c]);
            tm = fmaxf(tm, __shfl_xor_sync(0xffffffffu, tm, 1));
            tm = fmaxf(tm, __shfl_xor_sync(0xffffffffu, tm, 2));
            float mold = rm[r];
            float mnew = fmaxf(mold, tm);
            float lsum = 0.f;
            #pragma unroll
            for (int c = 0; c < 16; c++) {
                float p = __expf(prow[c] - mnew);
                prow[c] = p;
                lsum += p;
            }
            lsum += __shfl_xor_sync(0xffffffffu, lsum, 1);
            lsum += __shfl_xor_sync(0xffffffffu, lsum, 2);
            if (sub == 0) {
                float sc = __expf(mold - mnew);
                rs[r] = sc;
                rm[r] = mnew;
                rl[r] = rl[r] * sc + lsum;
            }
        }
        __syncthreads();
        float scl[4];
        #pragma unroll
        for (int i = 0; i < 4; i++) scl[i] = rs[ty*4+i];
        #pragma unroll
        for (int i = 0; i < 4; i++)
            #pragma unroll
            for (int j = 0; j < 4; j++) oacc[i][j] *= scl[i];
        for (int kk = 0; kk < 64; kk++) {
            float pf[4];
            #pragma unroll
            for (int i = 0; i < 4; i++) pf[i] = Ps[(ty*4+i)*68 + kk];
            float4 vv = *(const float4*)&Vs[kk*68 + tx*4];
            float vf[4] = {vv.x, vv.y, vv.z, vv.w};
            #pragma unroll
            for (int i = 0; i < 4; i++)
                #pragma unroll
                for (int j = 0; j < 4; j++)
                    oacc[i][j] = fmaf(pf[i], vf[j], oacc[i][j]);
        }
    }
    float linv[4];
    #pragma unroll
    for (int i = 0; i < 4; i++) linv[i] = 1.f / rl[ty*4+i];
    #pragma unroll
    for (int i = 0; i < 4; i++)
        #pragma unroll
        for (int j = 0; j < 4; j++)
            O[(size_t)(q0 + ty*4 + i) * DM + cbase + tx*4 + j] = oacc[i][j] * linv[i];
}

// ---------------- LayerNorm (W=1024), optional affine / residual add -------
template<bool AFF, bool RES>
__global__ void __launch_bounds__(256) ln_k(
    const float* __restrict__ X, const float* __restrict__ g,
    const float* __restrict__ b, const float* __restrict__ res,
    float* __restrict__ Y)
{
    const int row = blockIdx.x;
    const float* x = X + (size_t)row * DM;
    const int tid = threadIdx.x;
    float v[4];
    float s = 0.f;
    #pragma unroll
    for (int u = 0; u < 4; u++) { v[u] = x[tid + 256*u]; s += v[u]; }
    __shared__ float red[8];
    __shared__ float stat[2];
    #pragma unroll
    for (int off = 16; off; off >>= 1) s += __shfl_xor_sync(0xffffffffu, s, off);
    if ((tid & 31) == 0) red[tid >> 5] = s;
    __syncthreads();
    if (tid == 0) {
        float t = 0.f;
        for (int k2 = 0; k2 < 8; k2++) t += red[k2];
        stat[0] = t * (1.f/1024.f);
    }
    __syncthreads();
    float mu = stat[0];
    float q = 0.f;
    #pragma unroll
    for (int u = 0; u < 4; u++) { float d = v[u] - mu; q += d*d; }
    #pragma unroll
    for (int off = 16; off; off >>= 1) q += __shfl_xor_sync(0xffffffffu, q, off);
    if ((tid & 31) == 0) red[tid >> 5] = q;
    __syncthreads();
    if (tid == 0) {
        float t = 0.f;
        for (int k2 = 0; k2 < 8; k2++) t += red[k2];
        stat[1] = rsqrtf(t * (1.f/1024.f) + 1e-5f);
    }
    __syncthreads();
    float rstd = stat[1];
    float* y = Y + (size_t)row * DM;
    #pragma unroll
    for (int u = 0; u < 4; u++) {
        int c = tid + 256*u;
        float o = (v[u] - mu) * rstd;
        if (AFF) o = o * g[c] + b[c];
        if (RES) o += res[(size_t)row * DM + c];
        y[c] = o;
    }
}

// ---------------- depthwise causal conv1d (k=4) ----------------------------
__global__ void conv_k(const float* __restrict__ cw, const float* __restrict__ cb)
{
    int idx = blockIdx.x * blockDim.x + threadIdx.x;
    if (idx >= SEQ * DIN) return;
    int t = idx >> 11, c = idx & (DIN - 1);
    float acc = cb[c];
    #pragma unroll
    for (int k = 0; k < 4; k++) {
        int ts = t + k - 3;
        if (ts >= 0) acc = fmaf(cw[c*4 + k], g_xin[(size_t)ts * DIN + c], acc);
    }
    g_xc[idx] = acc;
}

// ---------------- B/C extraction: LN96 then LN16 ---------------------------
__global__ void bc_k()
{
    const int row = blockIdx.x;
    const int lane = threadIdx.x;
    const float* xr = g_xdbc + (size_t)row * XPN;
    float a0 = xr[lane], a1 = xr[lane + 32], a2 = xr[lane + 64];
    float s = a0 + a1 + a2;
    #pragma unroll
    for (int off = 16; off; off >>= 1) s += __shfl_xor_sync(0xffffffffu, s, off);
    float mu = s * (1.f/96.f);
    float d0 = a0-mu, d1 = a1-mu, d2 = a2-mu;
    float q = d0*d0 + d1*d1 + d2*d2;
    #pragma unroll
    for (int off = 16; off; off >>= 1) q += __shfl_xor_sync(0xffffffffu, q, off);
    float rstd = rsqrtf(q * (1.f/96.f) + 1e-5f);
    float vv = d2 * rstd;
    float hs = vv;
    #pragma unroll
    for (int off = 8; off; off >>= 1) hs += __shfl_xor_sync(0xffffffffu, hs, off);
    float m16 = hs * (1.f/16.f);
    float dd = vv - m16;
    float qq = dd * dd;
    #pragma unroll
    for (int off = 8; off; off >>= 1) qq += __shfl_xor_sync(0xffffffffu, qq, off);
    float o = dd * rsqrtf(qq * (1.f/16.f) + 1e-5f);
    if (lane < 16) g_Bm[row*16 + lane] = o;
    else           g_Cm[row*16 + lane - 16] = o;
}

// ---------------- build M and M^64 -----------------------------------------
__global__ void __launch_bounds__(256) buildM_k(const float* __restrict__ A)
{
    __shared__ float sred[256], sP[256];
    const int t = threadIdx.x;
    const int i = t >> 4, j = t & 15;
    float la = logf(fabsf(A[j*16 + i]) + 1e-8f);
    sred[t] = la;
    __syncthreads();
    for (int off = 128; off > 0; off >>= 1) {
        if (t < off) sred[t] = fminf(sred[t], sred[t + off]);
        __syncthreads();
    }
    float mn = sred[0];
    float Mv = expf(mn - la);
    Mv = fminf(fmaxf(Mv, 1e-4f), 1e4f);
    g_M[t] = Mv;
    sP[t] = Mv;
    __syncthreads();
    for (int it = 0; it < 6; ++it) {
        float acc = 0.f;
        #pragma unroll
        for (int k = 0; k < 16; k++) acc = fmaf(sP[i*16 + k], sP[k*16 + j], acc);
        __syncthreads();
        sP[t] = acc;
        __syncthreads();
    }
    g_M64[t] = sP[t];
}

// ---------------- chunked parallel scan ------------------------------------
__global__ void __launch_bounds__(1024) scan_k()
{
    __shared__ float sM[256], sM64[256], sE[32*16], sS[32*16];
    const int tid = threadIdx.x;
    if (tid < 256) { sM[tid] = g_M[tid]; sM64[tid] = g_M64[tid]; }
    __syncthreads();
    const int w = tid >> 5, lane = tid & 31;
    float mrow[16];
    #pragma unroll
    for (int j = 0; j < 16; j++) mrow[j] = (lane < 16) ? sM[lane*16 + j] : 0.f;
    const int t0 = w * 64;
    float h = 0.f;
    for (int k = 0; k < 64; k++) {
        float acc = (lane < 16) ? g_Bm[(t0 + k)*16 + lane] : 0.f;
        #pragma unroll
        for (int j = 0; j < 16; j++)
            acc = fmaf(mrow[j], __shfl_sync(0xffffffffu, h, j), acc);
        h = acc;
        if (lane < 16) g_H[(t0 + k)*16 + lane] = h;
    }
    if (lane < 16) sE[w*16 + lane] = h;
    __syncthreads();
    if (w == 0) {
        float m64row[16];
        #pragma unroll
        for (int j = 0; j < 16; j++) m64row[j] = (lane < 16) ? sM64[lane*16 + j] : 0.f;
        float sv2 = (lane < 16) ? sE[lane] : 0.f;
        if (lane < 16) sS[lane] = sv2;
        for (int c = 1; c < 32; c++) {
            float acc = (lane < 16) ? sE[c*16 + lane] : 0.f;
            #pragma unroll
            for (int j = 0; j < 16; j++)
                acc = fmaf(m64row[j], __shfl_sync(0xffffffffu, sv2, j), acc);
            sv2 = acc;
            if (lane < 16) sS[c*16 + lane] = sv2;
        }
    }
    __syncthreads();
    float v = (w > 0 && lane < 16) ? sS[(w-1)*16 + lane] : 0.f;
    for (int k = 0; k < 64; k++) {
        if (w > 0) {
            float acc = 0.f;
            #pragma unroll
            for (int j = 0; j < 16; j++)
                acc = fmaf(mrow[j], __shfl_sync(0xffffffffu, v, j), acc);
            v = acc;
        }
        float hh = 0.f, cc = 0.f;
        if (lane < 16) {
            hh = g_H[(t0 + k)*16 + lane] + v;
            cc = g_Cm[(t0 + k)*16 + lane];
        }
        float p = hh * cc;
        p += __shfl_xor_sync(0xffffffffu, p, 8);
        p += __shfl_xor_sync(0xffffffffu, p, 4);
        p += __shfl_xor_sync(0xffffffffu, p, 2);
        p += __shfl_xor_sync(0xffffffffu, p, 1);
        if (lane == 0) g_sv[t0 + k] = p;
    }
}

// ---------------- y = clip(x_in * (s + Dp), +-1000) ------------------------
__global__ void y_k(const float* __restrict__ Dp)
{
    int idx = blockIdx.x * blockDim.x + threadIdx.x;
    if (idx >= SEQ * DIN) return;
    int t = idx >> 11, c = idx & (DIN - 1);
    float vv = g_xin[idx] * (g_sv[t] + Dp[c]);
    g_y[idx] = fminf(fmaxf(vv, -1000.f), 1000.f);
}

// ---------------------------------------------------------------------------
extern "C" void kernel_launch(void* const* d_in, const int* in_sizes, int n_in,
                              void* d_out, int out_size)
{
    const float* x     = (const float*)d_in[0];
    const float* Wq    = (const float*)d_in[1];
    const float* bq    = (const float*)d_in[2];
    const float* Wk    = (const float*)d_in[3];
    const float* bk    = (const float*)d_in[4];
    const float* Wv    = (const float*)d_in[5];
    const float* bv    = (const float*)d_in[6];
    const float* Wo    = (const float*)d_in[7];
    const float* bo    = (const float*)d_in[8];
    const float* fc1w  = (const float*)d_in[9];
    const float* fc1b  = (const float*)d_in[10];
    const float* fc2w  = (const float*)d_in[11];
    const float* fc2b  = (const float*)d_in[12];
    const float* inw   = (const float*)d_in[13];
    const float* inb   = (const float*)d_in[14];
    const float* convw = (const float*)d_in[15];
    const float* convb = (const float*)d_in[16];
    const float* xpw   = (const float*)d_in[17];
    const float* xpb   = (const float*)d_in[18];
    const float* Amat  = (const float*)d_in[19];
    const float* Dp    = (const float*)d_in[20];
    // d_in[21] = dt_p: provably dead (delta cancels in the scan transition)
    const float* outw  = (const float*)d_in[22];
    const float* outb  = (const float*)d_in[23];
    const float* g1    = (const float*)d_in[24];
    const float* be1   = (const float*)d_in[25];
    const float* g2    = (const float*)d_in[26];
    const float* be2   = (const float*)d_in[27];
    const float* g3    = (const float*)d_in[28];
    const float* be3   = (const float*)d_in[29];
    float* out = (float*)d_out;

    float *p_ln, *p_q, *p_k, *p_v, *p_ao, *p_x1, *p_ln2, *p_xin, *p_xc,
          *p_xdbc, *p_y, *p_mt, *p_x2, *p_ff;
    cudaGetSymbolAddress((void**)&p_ln,   g_ln);
    cudaGetSymbolAddress((void**)&p_q,    g_q);
    cudaGetSymbolAddress((void**)&p_k,    g_k);
    cudaGetSymbolAddress((void**)&p_v,    g_v);
    cudaGetSymbolAddress((void**)&p_ao,   g_ao);
    cudaGetSymbolAddress((void**)&p_x1,   g_x1);
    cudaGetSymbolAddress((void**)&p_ln2,  g_ln2);
    cudaGetSymbolAddress((void**)&p_xin,  g_xin);
    cudaGetSymbolAddress((void**)&p_xc,   g_xc);
    cudaGetSymbolAddress((void**)&p_xdbc, g_xdbc);
    cudaGetSymbolAddress((void**)&p_y,    g_y);
    cudaGetSymbolAddress((void**)&p_mt,   g_mt);
    cudaGetSymbolAddress((void**)&p_x2,   g_x2);
    cudaGetSymbolAddress((void**)&p_ff,   g_ff);

    const int GEMM_SMEM = 2 * 4 * PER * (int)sizeof(unsigned);   // 81920
    cudaFuncSetAttribute(gemm_k<false,false>, cudaFuncAttributeMaxDynamicSharedMemorySize, GEMM_SMEM);
    cudaFuncSetAttribute(gemm_k<false,true>,  cudaFuncAttributeMaxDynamicSharedMemorySize, GEMM_SMEM);
    cudaFuncSetAttribute(gemm_k<true,false>,  cudaFuncAttributeMaxDynamicSharedMemorySize, GEMM_SMEM);

    const int ATTN_SMEM = (4*64*68 + 3*64) * (int)sizeof(float);
    cudaFuncSetAttribute(attn_k, cudaFuncAttributeMaxDynamicSharedMemorySize, ATTN_SMEM);

    // --- block 1: attention ---
    ln_k<true,false><<<SEQ, 256>>>(x, g1, be1, nullptr, p_ln);
    gemm_k<false,false><<<dim3(8,16), 256, GEMM_SMEM>>>(p_ln, Wq, bq, nullptr, p_q, SEQ, DM, DM);
    gemm_k<false,false><<<dim3(8,16), 256, GEMM_SMEM>>>(p_ln, Wk, bk, nullptr, p_k, SEQ, DM, DM);
    gemm_k<false,false><<<dim3(8,16), 256, GEMM_SMEM>>>(p_ln, Wv, bv, nullptr, p_v, SEQ, DM, DM);
    attn_k<<<dim3(SEQ/64, NH), 256, ATTN_SMEM>>>(p_q, p_k, p_v, p_ao);
    gemm_k<false,true><<<dim3(8,16), 256, GEMM_SMEM>>>(p_ao, Wo, bo, x, p_x1, SEQ, DM, DM);

    // --- block 2: mamba ---
    ln_k<true,false><<<SEQ, 256>>>(p_x1, g2, be2, nullptr, p_ln);
    ln_k<false,false><<<SEQ, 256>>>(p_ln, nullptr, nullptr, nullptr, p_ln2);
    gemm_k<false,false><<<dim3(16,16), 256, GEMM_SMEM>>>(p_ln2, inw, inb, nullptr, p_xin, SEQ, DIN, DM);
    conv_k<<<SEQ*DIN/256, 256>>>(convw, convb);
    gemm_k<false,false><<<dim3(1,16), 256, GEMM_SMEM>>>(p_xc, xpw, xpb, nullptr, p_xdbc, SEQ, XPN, DIN);
    bc_k<<<SEQ, 32>>>();
    buildM_k<<<1, 256>>>(Amat);
    scan_k<<<1, 1024>>>();
    y_k<<<SEQ*DIN/256, 256>>>(Dp);
    gemm_k<false,false><<<dim3(8,16), 256, GEMM_SMEM>>>(p_y, outw, outb, nullptr, p_mt, SEQ, DM, DIN);
    ln_k<false,true><<<SEQ, 256>>>(p_mt, nullptr, nullptr, p_x1, p_x2);

    // --- block 3: FFN ---
    ln_k<true,false><<<SEQ, 256>>>(p_x2, g3, be3, nullptr, p_ln);
    gemm_k<true,false><<<dim3(32,16), 256, GEMM_SMEM>>>(p_ln, fc1w, fc1b, nullptr, p_ff, SEQ, DFF, DM);
    gemm_k<false,true><<<dim3(8,16), 256, GEMM_SMEM>>>(p_ff, fc2w, fc2b, p_x2, out, SEQ, DM, DFF);
}

// round 7
// speedup vs baseline: 1.5223x; 1.0476x over previous
#include <cuda_runtime.h>
#include <stdint.h>
#include <math.h>

#define SEQ 2048
#define DM  1024
#define DFF 4096
#define DIN 2048
#define NH  16
#define XPN 96
#define DST 16
#define KSPL 8

// ---------------- fp32 scratch ---------------------------------------------
__device__ float g_ln  [SEQ*DM];     // fp32 temp (mamba LN stage 1)
__device__ float g_q   [SEQ*DM];
__device__ float g_k   [SEQ*DM];
__device__ float g_v   [SEQ*DM];
__device__ float g_x1  [SEQ*DM];
__device__ float g_xin [SEQ*DIN];
__device__ float g_xdbc[SEQ*XPN];
__device__ float g_Bm  [SEQ*DST];
__device__ float g_Cm  [SEQ*DST];
__device__ float g_H   [SEQ*DST];
__device__ float g_sv  [SEQ];
__device__ float g_mt  [SEQ*DM];
__device__ float g_x2  [SEQ*DM];
__device__ float g_M   [256];
__device__ float g_M64 [256];
__device__ float g_xpp [KSPL*SEQ*128];   // split-K partials for xp gemm

// ---------------- tf32 hi/lo split scratch (activations) -------------------
__device__ __align__(256) unsigned g_lnh[SEQ*DM],  g_lnl[SEQ*DM];
__device__ __align__(256) unsigned g_aoh[SEQ*DM],  g_aol[SEQ*DM];
__device__ __align__(256) unsigned g_xch[SEQ*DIN], g_xcl[SEQ*DIN];
__device__ __align__(256) unsigned g_yh [SEQ*DIN], g_yl [SEQ*DIN];
__device__ __align__(256) unsigned g_ffh[SEQ*DFF], g_ffl[SEQ*DFF];
// ---------------- tf32 hi/lo split scratch (weights) -----------------------
__device__ __align__(256) unsigned g_wqh[DM*DM],   g_wql[DM*DM];
__device__ __align__(256) unsigned g_wkh[DM*DM],   g_wkl[DM*DM];
__device__ __align__(256) unsigned g_wvh[DM*DM],   g_wvl[DM*DM];
__device__ __align__(256) unsigned g_woh[DM*DM],   g_wol[DM*DM];
__device__ __align__(256) unsigned g_inh[DIN*DM],  g_inl[DIN*DM];
__device__ __align__(256) unsigned g_xph[128*DIN], g_xpl[128*DIN];
__device__ __align__(256) unsigned g_oth[DM*DIN],  g_otl[DM*DIN];
__device__ __align__(256) unsigned g_f1h[DFF*DM],  g_f1l[DFF*DM];
__device__ __align__(256) unsigned g_f2h[DM*DFF],  g_f2l[DM*DFF];

// ---------------- TF32 helpers ---------------------------------------------
__device__ __forceinline__ unsigned f2tf(float f) {
    unsigned u;
    asm("cvt.rna.tf32.f32 %0, %1;" : "=r"(u) : "f"(f));
    return u;
}
__device__ __forceinline__ void split_tf(float v, unsigned& h, unsigned& l) {
    h = f2tf(v);
    l = f2tf(v - __uint_as_float(h));
}
__device__ __forceinline__ void mma_tf32(float* d, const unsigned* a,
                                         const unsigned* b, const float* c) {
    asm volatile(
        "mma.sync.aligned.m16n8k8.row.col.f32.tf32.tf32.f32 "
        "{%0,%1,%2,%3}, {%4,%5,%6,%7}, {%8,%9}, {%10,%11,%12,%13};\n"
        : "=f"(d[0]), "=f"(d[1]), "=f"(d[2]), "=f"(d[3])
        : "r"(a[0]), "r"(a[1]), "r"(a[2]), "r"(a[3]),
          "r"(b[0]), "r"(b[1]),
          "f"(c[0]), "f"(c[1]), "f"(c[2]), "f"(c[3]));
}
__device__ __forceinline__ void cp16(uint32_t s, const void* g) {
    asm volatile("cp.async.cg.shared.global [%0], [%1], 16;\n"
                 :: "r"(s), "l"(g) : "memory");
}

// ---------------- weight split: W (N,K) -> hi/lo (Npad,K), zero padding ----
__global__ void wsplit_k(const float* __restrict__ W,
                         unsigned* __restrict__ h, unsigned* __restrict__ l,
                         int N, int K, int Npad)
{
    int idx = blockIdx.x * blockDim.x + threadIdx.x;
    if (idx >= Npad * K) return;
    int row = idx / K;
    float v = (row < N) ? W[idx] : 0.f;
    split_tf(v, h[idx], l[idx]);
}

// ------- 3xTF32 GEMM, pre-split operands, cp.async 2-stage, BK=32 ----------
// A,B given as tf32 hi/lo arrays. A: (M,K), B: (Npad,K) both row-major.
// OM: 0 = fp32 out (+bias)(+res), 1 = GELU + split out, 2 = split-K partial.
// Tile 128x128, 256 thr = 2x4 warps, warp 64x32 via 4x4 m16n8k8, smem 144KB.
#define SSW 36
#define AW  (128*SSW)
template<int OM, bool GELU, bool RES>
__global__ void __launch_bounds__(256) gemm2(
    const unsigned* __restrict__ Ah, const unsigned* __restrict__ Al,
    const unsigned* __restrict__ Bh, const unsigned* __restrict__ Bl,
    const float* __restrict__ bias, const float* __restrict__ res,
    float* __restrict__ C, unsigned* __restrict__ Ch, unsigned* __restrict__ Cl,
    int M, int N, int K)
{
    extern __shared__ unsigned sm2[];   // [2 buf][Ah,Al,Bh,Bl][AW]
    const int tid = threadIdx.x;
    const int warp = tid >> 5, lane = tid & 31;
    const int g = lane >> 2, tig = lane & 3;
    const int wm = warp >> 2, wn = warp & 3;
    const int bm = blockIdx.y * 128, bn = blockIdx.x * 128;

    int kb = 0, klen = K;
    if (OM == 2) { klen = K / gridDim.z; kb = blockIdx.z * klen; }
    const int nk = klen >> 5;

    const uint32_t sbase = (uint32_t)__cvta_generic_to_shared(sm2);

    float acc[4][4][4];
    #pragma unroll
    for (int i = 0; i < 4; i++)
        #pragma unroll
        for (int j = 0; j < 4; j++)
            #pragma unroll
            for (int r = 0; r < 4; r++) acc[i][j][r] = 0.f;

    auto issue = [&](int kt, int buf) {
        const int k0 = kb + (kt << 5);
        #pragma unroll
        for (int u = 0; u < 4; u++) {
            const int id = tid + (u << 8);
            const int row = id >> 3, col = (id & 7) << 2;
            const int so = (row * SSW + col) * 4;
            const size_t ga = (size_t)(bm + row) * K + k0 + col;
            const size_t gb = (size_t)(bn + row) * K + k0 + col;
            cp16(sbase + ((buf*4 + 0) * AW) * 4 + so, Ah + ga);
            cp16(sbase + ((buf*4 + 1) * AW) * 4 + so, Al + ga);
            cp16(sbase + ((buf*4 + 2) * AW) * 4 + so, Bh + gb);
            cp16(sbase + ((buf*4 + 3) * AW) * 4 + so, Bl + gb);
        }
        asm volatile("cp.async.commit_group;\n" ::: "memory");
    };

    issue(0, 0);

    for (int kt = 0; kt < nk; kt++) {
        const int buf = kt & 1;
        if (kt + 1 < nk) {
            issue(kt + 1, buf ^ 1);
            asm volatile("cp.async.wait_group 1;\n" ::: "memory");
        } else {
            asm volatile("cp.async.wait_group 0;\n" ::: "memory");
        }
        __syncthreads();
        const unsigned* sAh = sm2 + (buf*4 + 0) * AW;
        const unsigned* sAl = sm2 + (buf*4 + 1) * AW;
        const unsigned* sBh = sm2 + (buf*4 + 2) * AW;
        const unsigned* sBl = sm2 + (buf*4 + 3) * AW;
        #pragma unroll
        for (int ks = 0; ks < 4; ks++) {
            const int kk = ks * 8;
            unsigned ah[4][4], al[4][4], bh[4][2], bl[4][2];
            #pragma unroll
            for (int i = 0; i < 4; i++) {
                const int o = (wm*64 + i*16 + g) * SSW + kk + tig;
                ah[i][0] = sAh[o];     ah[i][1] = sAh[o + 8*SSW];
                ah[i][2] = sAh[o + 4]; ah[i][3] = sAh[o + 8*SSW + 4];
                al[i][0] = sAl[o];     al[i][1] = sAl[o + 8*SSW];
                al[i][2] = sAl[o + 4]; al[i][3] = sAl[o + 8*SSW + 4];
            }
            #pragma unroll
            for (int j = 0; j < 4; j++) {
                const int o = (wn*32 + j*8 + g) * SSW + kk + tig;
                bh[j][0] = sBh[o]; bh[j][1] = sBh[o + 4];
                bl[j][0] = sBl[o]; bl[j][1] = sBl[o + 4];
            }
            #pragma unroll
            for (int i = 0; i < 4; i++)
                #pragma unroll
                for (int j = 0; j < 4; j++) {
                    mma_tf32(acc[i][j], ah[i], bh[j], acc[i][j]);
                    mma_tf32(acc[i][j], al[i], bh[j], acc[i][j]);
                    mma_tf32(acc[i][j], ah[i], bl[j], acc[i][j]);
                }
        }
        __syncthreads();
    }

    // epilogue
    #pragma unroll
    for (int i = 0; i < 4; i++) {
        const int r0 = bm + wm*64 + i*16 + g;
        const int r1 = r0 + 8;
        #pragma unroll
        for (int j = 0; j < 4; j++) {
            const int c = bn + wn*32 + j*8 + 2*tig;
            float v0 = acc[i][j][0], v1 = acc[i][j][1];
            float v2 = acc[i][j][2], v3 = acc[i][j][3];
            if (OM == 2) {
                float* Cp = C + (size_t)blockIdx.z * M * 128;
                *(float2*)&Cp[(size_t)r0*128 + c] = make_float2(v0, v1);
                *(float2*)&Cp[(size_t)r1*128 + c] = make_float2(v2, v3);
            } else if (c < N) {
                if (bias) {
                    const float b0 = bias[c], b1 = bias[c+1];
                    v0 += b0; v1 += b1; v2 += b0; v3 += b1;
                }
                if (RES) {
                    v0 += res[(size_t)r0*N + c];
                    v1 += res[(size_t)r0*N + c + 1];
                    v2 += res[(size_t)r1*N + c];
                    v3 += res[(size_t)r1*N + c + 1];
                }
                if (GELU) {
                    #define GLU(u) (0.5f*(u)*(1.f + tanhf(0.7978845608f*((u) + 0.044715f*(u)*(u)*(u)))))
                    v0 = GLU(v0); v1 = GLU(v1); v2 = GLU(v2); v3 = GLU(v3);
                    #undef GLU
                }
                if (OM == 0) {
                    *(float2*)&C[(size_t)r0*N + c] = make_float2(v0, v1);
                    *(float2*)&C[(size_t)r1*N + c] = make_float2(v2, v3);
                } else {   // OM==1: split output
                    split_tf(v0, Ch[(size_t)r0*N + c],     Cl[(size_t)r0*N + c]);
                    split_tf(v1, Ch[(size_t)r0*N + c + 1], Cl[(size_t)r0*N + c + 1]);
                    split_tf(v2, Ch[(size_t)r1*N + c],     Cl[(size_t)r1*N + c]);
                    split_tf(v3, Ch[(size_t)r1*N + c + 1], Cl[(size_t)r1*N + c + 1]);
                }
            }
        }
    }
}

// ---------------- reduce split-K partials for xp gemm ----------------------
__global__ void reduce_xp(const float* __restrict__ xpb)
{
    int idx = blockIdx.x * blockDim.x + threadIdx.x;
    if (idx >= SEQ * XPN) return;
    int m = idx / XPN, n = idx - m * XPN;
    float s = xpb[n];
    #pragma unroll
    for (int z = 0; z < KSPL; z++)
        s += g_xpp[((size_t)z * SEQ + m) * 128 + n];
    g_xdbc[idx] = s;
}

// ---------------- fused attention (flash-style, fp32), split output --------
__global__ void __launch_bounds__(256) attn_k(
    const float* __restrict__ Q, const float* __restrict__ K,
    const float* __restrict__ V, unsigned* __restrict__ Oh,
    unsigned* __restrict__ Ol)
{
    extern __shared__ float sm[];
    float* QT = sm;             // [64 d][68] transposed
    float* KT = QT + 64*68;
    float* Vs = KT + 64*68;
    float* Ps = Vs + 64*68;
    float* rm = Ps + 64*68;
    float* rl = rm + 64;
    float* rs = rl + 64;

    const int tid = threadIdx.x;
    const int tx = tid & 15, ty = tid >> 4;
    const int q0 = blockIdx.x * 64;
    const int cbase = blockIdx.y * 64;

    {
        int r = tid >> 2, seg = tid & 3;
        const float* qp = Q + (size_t)(q0 + r) * DM + cbase + seg * 16;
        #pragma unroll
        for (int u = 0; u < 4; u++) {
            float4 qv = *(const float4*)(qp + u * 4);
            int c = seg * 16 + u * 4;
            QT[(c+0)*68 + r] = qv.x;
            QT[(c+1)*68 + r] = qv.y;
            QT[(c+2)*68 + r] = qv.z;
            QT[(c+3)*68 + r] = qv.w;
        }
    }
    if (tid < 64) { rm[tid] = -1e30f; rl[tid] = 0.f; }
    float oacc[4][4];
    #pragma unroll
    for (int i = 0; i < 4; i++)
        #pragma unroll
        for (int j = 0; j < 4; j++) oacc[i][j] = 0.f;

    for (int kt = 0; kt < SEQ/64; kt++) {
        __syncthreads();
        {
            int r = tid >> 2, seg = tid & 3;
            const float* kp = K + (size_t)(kt*64 + r) * DM + cbase + seg * 16;
            const float* vp = V + (size_t)(kt*64 + r) * DM + cbase + seg * 16;
            #pragma unroll
            for (int u = 0; u < 4; u++) {
                float4 kv = *(const float4*)(kp + u * 4);
                int c = seg * 16 + u * 4;
                KT[(c+0)*68 + r] = kv.x;
                KT[(c+1)*68 + r] = kv.y;
                KT[(c+2)*68 + r] = kv.z;
                KT[(c+3)*68 + r] = kv.w;
                float4 vv = *(const float4*)(vp + u * 4);
                *(float4*)&Vs[r*68 + c] = vv;
            }
        }
        __syncthreads();
        float s[4][4];
        #pragma unroll
        for (int i = 0; i < 4; i++)
            #pragma unroll
            for (int j = 0; j < 4; j++) s[i][j] = 0.f;
        #pragma unroll 4
        for (int d = 0; d < 64; d++) {
            float4 qv = *(const float4*)&QT[d*68 + ty*4];
            float4 kv = *(const float4*)&KT[d*68 + tx*4];
            float qf[4] = {qv.x, qv.y, qv.z, qv.w};
            float kf[4] = {kv.x, kv.y, kv.z, kv.w};
            #pragma unroll
            for (int i = 0; i < 4; i++)
                #pragma unroll
                for (int j = 0; j < 4; j++)
                    s[i][j] = fmaf(qf[i], kf[j], s[i][j]);
        }
        #pragma unroll
        for (int i = 0; i < 4; i++)
            #pragma unroll
            for (int j = 0; j < 4; j++)
                Ps[(ty*4+i)*68 + tx*4 + j] = s[i][j] * 0.125f;
        __syncthreads();
        {
            int r = tid >> 2, sub = tid & 3;
            float* prow = Ps + r*68 + sub*16;
            float tm = -1e30f;
            #pragma unroll
            for (int c = 0; c < 16; c++) tm = fmaxf(tm, prow[c]);
            tm = fmaxf(tm, __shfl_xor_sync(0xffffffffu, tm, 1));
            tm = fmaxf(tm, __shfl_xor_sync(0xffffffffu, tm, 2));
            float mold = rm[r];
            float mnew = fmaxf(mold, tm);
            float lsum = 0.f;
            #pragma unroll
            for (int c = 0; c < 16; c++) {
                float p = __expf(prow[c] - mnew);
                prow[c] = p;
                lsum += p;
            }
            lsum += __shfl_xor_sync(0xffffffffu, lsum, 1);
            lsum += __shfl_xor_sync(0xffffffffu, lsum, 2);
            if (sub == 0) {
                float sc = __expf(mold - mnew);
                rs[r] = sc;
                rm[r] = mnew;
                rl[r] = rl[r] * sc + lsum;
            }
        }
        __syncthreads();
        float scl[4];
        #pragma unroll
        for (int i = 0; i < 4; i++) scl[i] = rs[ty*4+i];
        #pragma unroll
        for (int i = 0; i < 4; i++)
            #pragma unroll
            for (int j = 0; j < 4; j++) oacc[i][j] *= scl[i];
        for (int kk = 0; kk < 64; kk++) {
            float pf[4];
            #pragma unroll
            for (int i = 0; i < 4; i++) pf[i] = Ps[(ty*4+i)*68 + kk];
            float4 vv = *(const float4*)&Vs[kk*68 + tx*4];
            float vf[4] = {vv.x, vv.y, vv.z, vv.w};
            #pragma unroll
            for (int i = 0; i < 4; i++)
                #pragma unroll
                for (int j = 0; j < 4; j++)
                    oacc[i][j] = fmaf(pf[i], vf[j], oacc[i][j]);
        }
    }
    float linv[4];
    #pragma unroll
    for (int i = 0; i < 4; i++) linv[i] = 1.f / rl[ty*4+i];
    #pragma unroll
    for (int i = 0; i < 4; i++)
        #pragma unroll
        for (int j = 0; j < 4; j++) {
            const size_t o = (size_t)(q0 + ty*4 + i) * DM + cbase + tx*4 + j;
            split_tf(oacc[i][j] * linv[i], Oh[o], Ol[o]);
        }
}

// ---------------- LayerNorm: optional affine/residual, fp32 and/or split ---
template<bool AFF, bool RES, bool WF, bool WS>
__global__ void __launch_bounds__(256) ln_k(
    const float* __restrict__ X, const float* __restrict__ g,
    const float* __restrict__ b, const float* __restrict__ res,
    float* __restrict__ Y, unsigned* __restrict__ Yh, unsigned* __restrict__ Yl)
{
    const int row = blockIdx.x;
    const float* x = X + (size_t)row * DM;
    const int tid = threadIdx.x;
    float v[4];
    float s = 0.f;
    #pragma unroll
    for (int u = 0; u < 4; u++) { v[u] = x[tid + 256*u]; s += v[u]; }
    __shared__ float red[8];
    __shared__ float stat[2];
    #pragma unroll
    for (int off = 16; off; off >>= 1) s += __shfl_xor_sync(0xffffffffu, s, off);
    if ((tid & 31) == 0) red[tid >> 5] = s;
    __syncthreads();
    if (tid == 0) {
        float t = 0.f;
        for (int k2 = 0; k2 < 8; k2++) t += red[k2];
        stat[0] = t * (1.f/1024.f);
    }
    __syncthreads();
    float mu = stat[0];
    float q = 0.f;
    #pragma unroll
    for (int u = 0; u < 4; u++) { float d = v[u] - mu; q += d*d; }
    #pragma unroll
    for (int off = 16; off; off >>= 1) q += __shfl_xor_sync(0xffffffffu, q, off);
    if ((tid & 31) == 0) red[tid >> 5] = q;
    __syncthreads();
    if (tid == 0) {
        float t = 0.f;
        for (int k2 = 0; k2 < 8; k2++) t += red[k2];
        stat[1] = rsqrtf(t * (1.f/1024.f) + 1e-5f);
    }
    __syncthreads();
    float rstd = stat[1];
    #pragma unroll
    for (int u = 0; u < 4; u++) {
        int c = tid + 256*u;
        float o = (v[u] - mu) * rstd;
        if (AFF) o = o * g[c] + b[c];
        if (RES) o += res[(size_t)row * DM + c];
        const size_t idx = (size_t)row * DM + c;
        if (WF) Y[idx] = o;
        if (WS) split_tf(o, Yh[idx], Yl[idx]);
    }
}

// ---------------- depthwise causal conv1d (k=4), split output --------------
__global__ void conv_k(const float* __restrict__ cw, const float* __restrict__ cb)
{
    int idx = blockIdx.x * blockDim.x + threadIdx.x;
    if (idx >= SEQ * DIN) return;
    int t = idx >> 11, c = idx & (DIN - 1);
    float acc = cb[c];
    #pragma unroll
    for (int k = 0; k < 4; k++) {
        int ts = t + k - 3;
        if (ts >= 0) acc = fmaf(cw[c*4 + k], g_xin[(size_t)ts * DIN + c], acc);
    }
    split_tf(acc, g_xch[idx], g_xcl[idx]);
}

// ---------------- B/C extraction: LN96 then LN16 ---------------------------
__global__ void bc_k()
{
    const int row = blockIdx.x;
    const int lane = threadIdx.x;
    const float* xr = g_xdbc + (size_t)row * XPN;
    float a0 = xr[lane], a1 = xr[lane + 32], a2 = xr[lane + 64];
    float s = a0 + a1 + a2;
    #pragma unroll
    for (int off = 16; off; off >>= 1) s += __shfl_xor_sync(0xffffffffu, s, off);
    float mu = s * (1.f/96.f);
    float d0 = a0-mu, d1 = a1-mu, d2 = a2-mu;
    float q = d0*d0 + d1*d1 + d2*d2;
    #pragma unroll
    for (int off = 16; off; off >>= 1) q += __shfl_xor_sync(0xffffffffu, q, off);
    float rstd = rsqrtf(q * (1.f/96.f) + 1e-5f);
    float vv = d2 * rstd;
    float hs = vv;
    #pragma unroll
    for (int off = 8; off; off >>= 1) hs += __shfl_xor_sync(0xffffffffu, hs, off);
    float m16 = hs * (1.f/16.f);
    float dd = vv - m16;
    float qq = dd * dd;
    #pragma unroll
    for (int off = 8; off; off >>= 1) qq += __shfl_xor_sync(0xffffffffu, qq, off);
    float o = dd * rsqrtf(qq * (1.f/16.f) + 1e-5f);
    if (lane < 16) g_Bm[row*16 + lane] = o;
    else           g_Cm[row*16 + lane - 16] = o;
}

// ---------------- build M and M^64 -----------------------------------------
__global__ void __launch_bounds__(256) buildM_k(const float* __restrict__ A)
{
    __shared__ float sred[256], sP[256];
    const int t = threadIdx.x;
    const int i = t >> 4, j = t & 15;
    float la = logf(fabsf(A[j*16 + i]) + 1e-8f);
    sred[t] = la;
    __syncthreads();
    for (int off = 128; off > 0; off >>= 1) {
        if (t < off) sred[t] = fminf(sred[t], sred[t + off]);
        __syncthreads();
    }
    float mn = sred[0];
    float Mv = expf(mn - la);
    Mv = fminf(fmaxf(Mv, 1e-4f), 1e4f);
    g_M[t] = Mv;
    sP[t] = Mv;
    __syncthreads();
    for (int it = 0; it < 6; ++it) {
        float acc = 0.f;
        #pragma unroll
        for (int k = 0; k < 16; k++) acc = fmaf(sP[i*16 + k], sP[k*16 + j], acc);
        __syncthreads();
        sP[t] = acc;
        __syncthreads();
    }
    g_M64[t] = sP[t];
}

// ---------------- chunked parallel scan ------------------------------------
__global__ void __launch_bounds__(1024) scan_k()
{
    __shared__ float sM[256], sM64[256], sE[32*16], sS[32*16];
    const int tid = threadIdx.x;
    if (tid < 256) { sM[tid] = g_M[tid]; sM64[tid] = g_M64[tid]; }
    __syncthreads();
    const int w = tid >> 5, lane = tid & 31;
    float mrow[16];
    #pragma unroll
    for (int j = 0; j < 16; j++) mrow[j] = (lane < 16) ? sM[lane*16 + j] : 0.f;
    const int t0 = w * 64;
    float h = 0.f;
    for (int k = 0; k < 64; k++) {
        float acc = (lane < 16) ? g_Bm[(t0 + k)*16 + lane] : 0.f;
        #pragma unroll
        for (int j = 0; j < 16; j++)
            acc = fmaf(mrow[j], __shfl_sync(0xffffffffu, h, j), acc);
        h = acc;
        if (lane < 16) g_H[(t0 + k)*16 + lane] = h;
    }
    if (lane < 16) sE[w*16 + lane] = h;
    __syncthreads();
    if (w == 0) {
        float m64row[16];
        #pragma unroll
        for (int j = 0; j < 16; j++) m64row[j] = (lane < 16) ? sM64[lane*16 + j] : 0.f;
        float sv2 = (lane < 16) ? sE[lane] : 0.f;
        if (lane < 16) sS[lane] = sv2;
        for (int c = 1; c < 32; c++) {
            float acc = (lane < 16) ? sE[c*16 + lane] : 0.f;
            #pragma unroll
            for (int j = 0; j < 16; j++)
                acc = fmaf(m64row[j], __shfl_sync(0xffffffffu, sv2, j), acc);
            sv2 = acc;
            if (lane < 16) sS[c*16 + lane] = sv2;
        }
    }
    __syncthreads();
    float v = (w > 0 && lane < 16) ? sS[(w-1)*16 + lane] : 0.f;
    for (int k = 0; k < 64; k++) {
        if (w > 0) {
            float acc = 0.f;
            #pragma unroll
            for (int j = 0; j < 16; j++)
                acc = fmaf(mrow[j], __shfl_sync(0xffffffffu, v, j), acc);
            v = acc;
        }
        float hh = 0.f, cc = 0.f;
        if (lane < 16) {
            hh = g_H[(t0 + k)*16 + lane] + v;
            cc = g_Cm[(t0 + k)*16 + lane];
        }
        float p = hh * cc;
        p += __shfl_xor_sync(0xffffffffu, p, 8);
        p += __shfl_xor_sync(0xffffffffu, p, 4);
        p += __shfl_xor_sync(0xffffffffu, p, 2);
        p += __shfl_xor_sync(0xffffffffu, p, 1);
        if (lane == 0) g_sv[t0 + k] = p;
    }
}

// ---------------- y = clip(x_in * (s + Dp), +-1000), split output ----------
__global__ void y_k(const float* __restrict__ Dp)
{
    int idx = blockIdx.x * blockDim.x + threadIdx.x;
    if (idx >= SEQ * DIN) return;
    int t = idx >> 11, c = idx & (DIN - 1);
    float vv = g_xin[idx] * (g_sv[t] + Dp[c]);
    vv = fminf(fmaxf(vv, -1000.f), 1000.f);
    split_tf(vv, g_yh[idx], g_yl[idx]);
}

// ---------------------------------------------------------------------------
extern "C" void kernel_launch(void* const* d_in, const int* in_sizes, int n_in,
                              void* d_out, int out_size)
{
    const float* x     = (const float*)d_in[0];
    const float* Wq    = (const float*)d_in[1];
    const float* bq    = (const float*)d_in[2];
    const float* Wk    = (const float*)d_in[3];
    const float* bk    = (const float*)d_in[4];
    const float* Wv    = (const float*)d_in[5];
    const float* bv    = (const float*)d_in[6];
    const float* Wo    = (const float*)d_in[7];
    const float* bo    = (const float*)d_in[8];
    const float* fc1w  = (const float*)d_in[9];
    const float* fc1b  = (const float*)d_in[10];
    const float* fc2w  = (const float*)d_in[11];
    const float* fc2b  = (const float*)d_in[12];
    const float* inw   = (const float*)d_in[13];
    const float* inb   = (const float*)d_in[14];
    const float* convw = (const float*)d_in[15];
    const float* convb = (const float*)d_in[16];
    const float* xpw   = (const float*)d_in[17];
    const float* xpb   = (const float*)d_in[18];
    const float* Amat  = (const float*)d_in[19];
    const float* Dp    = (const float*)d_in[20];
    // d_in[21] = dt_p: provably dead (delta cancels in the scan transition)
    const float* outw  = (const float*)d_in[22];
    const float* outb  = (const float*)d_in[23];
    const float* g1    = (const float*)d_in[24];
    const float* be1   = (const float*)d_in[25];
    const float* g2    = (const float*)d_in[26];
    const float* be2   = (const float*)d_in[27];
    const float* g3    = (const float*)d_in[28];
    const float* be3   = (const float*)d_in[29];
    float* out = (float*)d_out;

    // symbol addresses
    float *p_ln, *p_q, *p_k, *p_v, *p_x1, *p_xin, *p_mt, *p_x2, *p_xpp;
    unsigned *p_lnh,*p_lnl,*p_aoh,*p_aol,*p_xch,*p_xcl,*p_yh,*p_yl,*p_ffh,*p_ffl;
    unsigned *p_wqh,*p_wql,*p_wkh,*p_wkl,*p_wvh,*p_wvl,*p_woh,*p_wol;
    unsigned *p_inh,*p_inl,*p_xph,*p_xpl,*p_oth,*p_otl,*p_f1h,*p_f1l,*p_f2h,*p_f2l;
    cudaGetSymbolAddress((void**)&p_ln,  g_ln);
    cudaGetSymbolAddress((void**)&p_q,   g_q);
    cudaGetSymbolAddress((void**)&p_k,   g_k);
    cudaGetSymbolAddress((void**)&p_v,   g_v);
    cudaGetSymbolAddress((void**)&p_x1,  g_x1);
    cudaGetSymbolAddress((void**)&p_xin, g_xin);
    cudaGetSymbolAddress((void**)&p_mt,  g_mt);
    cudaGetSymbolAddress((void**)&p_x2,  g_x2);
    cudaGetSymbolAddress((void**)&p_xpp, g_xpp);
    cudaGetSymbolAddress((void**)&p_lnh, g_lnh); cudaGetSymbolAddress((void**)&p_lnl, g_lnl);
    cudaGetSymbolAddress((void**)&p_aoh, g_aoh); cudaGetSymbolAddress((void**)&p_aol, g_aol);
    cudaGetSymbolAddress((void**)&p_xch, g_xch); cudaGetSymbolAddress((void**)&p_xcl, g_xcl);
    cudaGetSymbolAddress((void**)&p_yh,  g_yh);  cudaGetSymbolAddress((void**)&p_yl,  g_yl);
    cudaGetSymbolAddress((void**)&p_ffh, g_ffh); cudaGetSymbolAddress((void**)&p_ffl, g_ffl);
    cudaGetSymbolAddress((void**)&p_wqh, g_wqh); cudaGetSymbolAddress((void**)&p_wql, g_wql);
    cudaGetSymbolAddress((void**)&p_wkh, g_wkh); cudaGetSymbolAddress((void**)&p_wkl, g_wkl);
    cudaGetSymbolAddress((void**)&p_wvh, g_wvh); cudaGetSymbolAddress((void**)&p_wvl, g_wvl);
    cudaGetSymbolAddress((void**)&p_woh, g_woh); cudaGetSymbolAddress((void**)&p_wol, g_wol);
    cudaGetSymbolAddress((void**)&p_inh, g_inh); cudaGetSymbolAddress((void**)&p_inl, g_inl);
    cudaGetSymbolAddress((void**)&p_xph, g_xph); cudaGetSymbolAddress((void**)&p_xpl, g_xpl);
    cudaGetSymbolAddress((void**)&p_oth, g_oth); cudaGetSymbolAddress((void**)&p_otl, g_otl);
    cudaGetSymbolAddress((void**)&p_f1h, g_f1h); cudaGetSymbolAddress((void**)&p_f1l, g_f1l);
    cudaGetSymbolAddress((void**)&p_f2h, g_f2h); cudaGetSymbolAddress((void**)&p_f2l, g_f2l);

    const int GEMM_SMEM = 2 * 4 * AW * (int)sizeof(unsigned);   // 147456
    cudaFuncSetAttribute(gemm2<0,false,false>, cudaFuncAttributeMaxDynamicSharedMemorySize, GEMM_SMEM);
    cudaFuncSetAttribute(gemm2<0,false,true>,  cudaFuncAttributeMaxDynamicSharedMemorySize, GEMM_SMEM);
    cudaFuncSetAttribute(gemm2<1,true,false>,  cudaFuncAttributeMaxDynamicSharedMemorySize, GEMM_SMEM);
    cudaFuncSetAttribute(gemm2<2,false,false>, cudaFuncAttributeMaxDynamicSharedMemorySize, GEMM_SMEM);
    const int ATTN_SMEM = (4*64*68 + 3*64) * (int)sizeof(float);
    cudaFuncSetAttribute(attn_k, cudaFuncAttributeMaxDynamicSharedMemorySize, ATTN_SMEM);

    // --- weight pre-split (runs every call; deterministic) ---
    wsplit_k<<<(DM*DM+255)/256, 256>>>(Wq,   p_wqh, p_wql, DM,  DM,  DM);
    wsplit_k<<<(DM*DM+255)/256, 256>>>(Wk,   p_wkh, p_wkl, DM,  DM,  DM);
    wsplit_k<<<(DM*DM+255)/256, 256>>>(Wv,   p_wvh, p_wvl, DM,  DM,  DM);
    wsplit_k<<<(DM*DM+255)/256, 256>>>(Wo,   p_woh, p_wol, DM,  DM,  DM);
    wsplit_k<<<(DIN*DM+255)/256, 256>>>(inw, p_inh, p_inl, DIN, DM,  DIN);
    wsplit_k<<<(128*DIN+255)/256, 256>>>(xpw,p_xph, p_xpl, XPN, DIN, 128);
    wsplit_k<<<(DM*DIN+255)/256, 256>>>(outw,p_oth, p_otl, DM,  DIN, DM);
    wsplit_k<<<(DFF*DM+255)/256, 256>>>(fc1w,p_f1h, p_f1l, DFF, DM,  DFF);
    wsplit_k<<<(DM*DFF+255)/256, 256>>>(fc2w,p_f2h, p_f2l, DM,  DFF, DM);

    // --- block 1: attention ---
    ln_k<true,false,false,true><<<SEQ, 256>>>(x, g1, be1, nullptr, nullptr, p_lnh, p_lnl);
    gemm2<0,false,false><<<dim3(8,16), 256, GEMM_SMEM>>>(p_lnh,p_lnl, p_wqh,p_wql, bq, nullptr, p_q, nullptr,nullptr, SEQ, DM, DM);
    gemm2<0,false,false><<<dim3(8,16), 256, GEMM_SMEM>>>(p_lnh,p_lnl, p_wkh,p_wkl, bk, nullptr, p_k, nullptr,nullptr, SEQ, DM, DM);
    gemm2<0,false,false><<<dim3(8,16), 256, GEMM_SMEM>>>(p_lnh,p_lnl, p_wvh,p_wvl, bv, nullptr, p_v, nullptr,nullptr, SEQ, DM, DM);
    attn_k<<<dim3(SEQ/64, NH), 256, ATTN_SMEM>>>(p_q, p_k, p_v, p_aoh, p_aol);
    gemm2<0,false,true><<<dim3(8,16), 256, GEMM_SMEM>>>(p_aoh,p_aol, p_woh,p_wol, bo, x, p_x1, nullptr,nullptr, SEQ, DM, DM);

    // --- block 2: mamba ---
    ln_k<true,false,true,false><<<SEQ, 256>>>(p_x1, g2, be2, nullptr, p_ln, nullptr, nullptr);
    ln_k<false,false,false,true><<<SEQ, 256>>>(p_ln, nullptr, nullptr, nullptr, nullptr, p_lnh, p_lnl);
    gemm2<0,false,false><<<dim3(16,16), 256, GEMM_SMEM>>>(p_lnh,p_lnl, p_inh,p_inl, inb, nullptr, p_xin, nullptr,nullptr, SEQ, DIN, DM);
    conv_k<<<SEQ*DIN/256, 256>>>(convw, convb);
    gemm2<2,false,false><<<dim3(1,16,KSPL), 256, GEMM_SMEM>>>(p_xch,p_xcl, p_xph,p_xpl, nullptr, nullptr, p_xpp, nullptr,nullptr, SEQ, 128, DIN);
    reduce_xp<<<(SEQ*XPN+255)/256, 256>>>(xpb);
    bc_k<<<SEQ, 32>>>();
    buildM_k<<<1, 256>>>(Amat);
    scan_k<<<1, 1024>>>();
    y_k<<<SEQ*DIN/256, 256>>>(Dp);
    gemm2<0,false,false><<<dim3(8,16), 256, GEMM_SMEM>>>(p_yh,p_yl, p_oth,p_otl, outb, nullptr, p_mt, nullptr,nullptr, SEQ, DM, DIN);
    ln_k<false,true,true,false><<<SEQ, 256>>>(p_mt, nullptr, nullptr, p_x1, p_x2, nullptr, nullptr);

    // --- block 3: FFN ---
    ln_k<true,false,false,true><<<SEQ, 256>>>(p_x2, g3, be3, nullptr, nullptr, p_lnh, p_lnl);
    gemm2<1,true,false><<<dim3(32,16), 256, GEMM_SMEM>>>(p_lnh,p_lnl, p_f1h,p_f1l, fc1b, nullptr, nullptr, p_ffh,p_ffl, SEQ, DFF, DM);
    gemm2<0,false,true><<<dim3(8,16), 256, GEMM_SMEM>>>(p_ffh,p_ffl, p_f2h,p_f2l, fc2b, p_x2, out, nullptr,nullptr, SEQ, DM, DFF);
}